// round 14
// baseline (speedup 1.0000x reference)
#include <cuda_runtime.h>

// x shape (N=2, D=192, H=256, W=512), float32.
#define DIMD 192
#define HWD  131072          // H*W
#define BLK  512             // threads per block
#define COLS 128             // pixel columns per block (4 threads / column)
#define NPIX 262144          // N*H*W
#define CST  129             // ODD smem row stride: bank = (d + c) & 31
#define SMEM_BYTES (DIMD * CST * 4)   // 99072 B -> 2 CTAs/SM (32 warps/SM)

// Correctly-rounded a/5 (Markstein step, exact seed 0.2f) — bit-identical to
// __fdiv_rn(a,5); 3 FMA-pipe ops. Validated rounds 5-13.
__device__ __forceinline__ float qdiv5(float a)
{
    const float y  = 0.2f;
    float q0 = a * y;
    float r  = fmaf(-5.0f, q0, a);
    return fmaf(r, y, q0);
}

// Ordered 2-way merge: strict > so ties keep the LOWER-index side
// (first-occurrence argmax). selfLow says whether our indices precede partner's.
__device__ __forceinline__ void merge2(bool selfLow, float aq, int ai,
                                       float bq, int bi, float& q, int& i)
{
    float lq = selfLow ? aq : bq;  int li = selfLow ? ai : bi;
    float hq = selfLow ? bq : aq;  int hi = selfLow ? bi : ai;
    bool u = (hq > lq);
    q = u ? hq : lq;
    i = u ? hi : li;
}

// Direction-unified slope scan. Right (dir=+1): first strictly-increasing step
// after idx -> returns ir. Left (dir=-1): last strictly-decreasing step at or
// below idx -> returns il. Both are "advance while q(p) <= tracked".
// Blur: exact reference add order on raw x, zero padding; HASZ zeroes the
// blur VALUE on [ZA,ZB] (x_blur * ~mask semantics).
template<bool HASZ>
__device__ __forceinline__ int dir_scan(const float* __restrict__ sp, int idx,
                                        float bq, int dir, int ZA, int ZB)
{
    int   pos = idx;
    float val = bq;
    while (true) {
        int p = pos + dir;
        if ((unsigned)p >= (unsigned)DIMD) break;    // sentinel at both ends
        float q;
        if (HASZ && p >= ZA && p <= ZB) {
            q = 0.0f;
        } else {
            float a = (p >= 2)        ? sp[(p - 2) * CST] : 0.0f;
            a = a + ((p >= 1)         ? sp[(p - 1) * CST] : 0.0f);
            a = a +                     sp[p * CST];
            a = a + ((p + 1 < DIMD)   ? sp[(p + 1) * CST] : 0.0f);
            a = a + ((p + 2 < DIMD)   ? sp[(p + 2) * CST] : 0.0f);
            q = qdiv5(a);
        }
        if (q > val) break;
        val = q; pos = p;
    }
    return pos;
}

// Continue argmax of blur(raw x) over d in [a, bEnd), rolling window.
__device__ __forceinline__ void seg_argmax(const float* __restrict__ sp, int a, int bEnd,
                                           float& bestQ, int& idx)
{
    if (a >= bEnd) return;
    float w0 = (a - 2 >= 0)   ? sp[(a - 2) * CST] : 0.0f;
    float w1 = (a - 1 >= 0)   ? sp[(a - 1) * CST] : 0.0f;
    float w2 =                  sp[a * CST];
    float w3 = (a + 1 < DIMD) ? sp[(a + 1) * CST] : 0.0f;
    #pragma unroll 2
    for (int d = a; d < bEnd; ++d) {
        float w4 = (d + 2 < DIMD) ? sp[(d + 2) * CST] : 0.0f;
        float q  = qdiv5((((w0 + w1) + w2) + w3) + w4);
        bool  u  = (q > bestQ);             // strict -> first occurrence
        bestQ = u ? q : bestQ;
        idx   = u ? d : idx;
        w0 = w1; w1 = w2; w2 = w3; w3 = w4;
    }
}

__global__ void __launch_bounds__(BLK, 2)
dme_kernel(const float* __restrict__ x, float* __restrict__ out)
{
    extern __shared__ float s[];                // [DIMD][CST], col c at s[d*CST+c]
    const int tid  = threadIdx.x;
    const int c    = tid >> 2;                  // column 0..127
    const int r    = tid & 3;                   // role 0..3: d-quarter [48r, 48r+48)
    const int sr   = r & 1;                     // sub-role: 0 = right/y, 1 = left/z
    const int pix0 = blockIdx.x * COLS;         // blocks never straddle n
    const int n    = pix0 >> 17;
    const int hw0  = pix0 & (HWD - 1);
    const float* __restrict__ gb = x + (size_t)n * DIMD * HWD + hw0;

    // ---- stage-in: 48 scalar loads/thread; coalesced LDG, conflict-free STS ----
    #pragma unroll 8
    for (int i = 0; i < (DIMD * COLS) / BLK; ++i) {   // 48 iters
        int flat = i * BLK + tid;
        int d    = flat >> 7;                   // /COLS
        int cc   = flat & (COLS - 1);
        s[d * CST + cc] = gb[(size_t)d * HWD + cc];
    }
    __syncthreads();

    const float* __restrict__ sp = s + c;       // this column's base

    // ---- pass-1 argmax over blur: one 48-iter chain per role ----
    const int base = 48 * r;
    float bq1 = -1.0f; int bi1 = 0;
    {
        float w0 = (base >= 2) ? sp[(base - 2) * CST] : 0.0f;   // zeros only r=0
        float w1 = (base >= 1) ? sp[(base - 1) * CST] : 0.0f;
        float w2 = sp[base * CST];
        float w3 = sp[(base + 1) * CST];
        #pragma unroll 2
        for (int j = 0; j < 46; ++j) {          // d+2 <= 191 for all roles
            float w4 = sp[(base + j + 2) * CST];
            float q  = qdiv5((((w0 + w1) + w2) + w3) + w4);
            bool  u  = (q > bq1);
            bq1 = u ? q : bq1;
            bi1 = u ? (base + j) : bi1;
            w0 = w1; w1 = w2; w2 = w3; w3 = w4;
        }
        #pragma unroll
        for (int j = 46; j < 48; ++j) {         // tail: only r=3 pads with zeros
            int p = base + j + 2;
            float w4 = (p < DIMD) ? sp[p * CST] : 0.0f;
            float q  = qdiv5((((w0 + w1) + w2) + w3) + w4);
            bool  u  = (q > bq1);
            bq1 = u ? q : bq1;
            bi1 = u ? (base + j) : bi1;
            w0 = w1; w1 = w2; w2 = w3; w3 = w4;
        }
    }
    // ordered 2-stage merge (roles ascend in d)
    float bestQ; int idx;
    {
        float oq = __shfl_xor_sync(0xffffffffu, bq1, 1);
        int   oi = __shfl_xor_sync(0xffffffffu, bi1, 1);
        float mq; int mi;
        merge2((r & 1) == 0, bq1, bi1, oq, oi, mq, mi);
        float pq = __shfl_xor_sync(0xffffffffu, mq, 2);
        int   pi = __shfl_xor_sync(0xffffffffu, mi, 2);
        merge2(r < 2, mq, mi, pq, pi, bestQ, idx);
    }

    // ---- modal interval 1: right scan on sr=0, left scan on sr=1 (same code) ----
    const int dir = sr ? -1 : 1;
    int lo1, hi1;
    {
        int mine  = dir_scan<false>(sp, idx, bestQ, dir, 0, -1);
        int other = __shfl_xor_sync(0xffffffffu, mine, 1);
        int ir = sr ? other : mine;
        int il = sr ? mine  : other;
        int dev = 2 * idx - ir - il; if (dev < 0) dev = -dev;
        if (dev < 3) { lo1 = il; hi1 = ir; }
        else { int rr = min(ir - idx, idx - il); lo1 = idx - rr; hi1 = idx + rr; }
    }

    // ---- pass-2 argmax over complement of [lo1,hi1], split by role quarter ----
    float bq2l = -1.0f; int bi2l = 0;
    seg_argmax(sp, base, min(lo1, base + 48), bq2l, bi2l);
    seg_argmax(sp, max(hi1 + 1, base), base + 48, bq2l, bi2l);
    float bq2; int idx2;
    {
        float oq = __shfl_xor_sync(0xffffffffu, bq2l, 1);
        int   oi = __shfl_xor_sync(0xffffffffu, bi2l, 1);
        float mq; int mi;
        merge2((r & 1) == 0, bq2l, bi2l, oq, oi, mq, mi);
        float pq = __shfl_xor_sync(0xffffffffu, mq, 2);
        int   pi = __shfl_xor_sync(0xffffffffu, mi, 2);
        merge2(r < 2, mq, mi, pq, pi, bq2, idx2);
    }

    // ---- modal interval 2 (blur zeroed on [lo1,hi1]) ----
    int lo2, hi2;
    {
        int mine  = dir_scan<true>(sp, idx2, bq2, dir, lo1, hi1);
        int other = __shfl_xor_sync(0xffffffffu, mine, 1);
        int ir = sr ? other : mine;
        int il = sr ? mine  : other;
        int dev = 2 * idx2 - ir - il; if (dev < 0) dev = -dev;
        if (dev < 3) { lo2 = il; hi2 = ir; }
        else { int rr = min(ir - idx2, idx2 - il); lo2 = idx2 - rr; hi2 = idx2 + rr; }
    }

    // ---- reductions: sr=0 -> y over [lo1,hi1]; sr=1 -> z over [lo2,hi2]\[lo1,hi1]
    //      (identical sequential accumulation order to the validated round-13) ----
    const int A  = sr ? lo2 : lo1;
    const int B  = sr ? hi2 : hi1;
    const int E0 = sr ? lo1 : 1;
    const int E1 = sr ? hi1 : 0;
    float ss = 0.0f, sd = 0.0f;
    for (int d = A; d <= B; ++d) {
        if (d >= E0 && d <= E1) continue;
        float v = sp[d * CST];
        ss += v; sd = fmaf(v, (float)d, sd);
    }
    float os = __shfl_xor_sync(0xffffffffu, ss, 1);
    float od = __shfl_xor_sync(0xffffffffu, sd, 1);
    const float sy  = sr ? os : ss, syd = sr ? od : sd;
    const float sz  = sr ? ss : os, szd = sr ? sd : od;

    if (r == 0) {
        const bool  py  = (sy >= sz);
        const float num = py ? syd : szd;
        const float den = py ? sy  : sz;        // > 0 guaranteed (x > 0)
        out[pix0 + c] = __fdiv_rn(num, den);
    }
}

extern "C" void kernel_launch(void* const* d_in, const int* in_sizes, int n_in,
                              void* d_out, int out_size)
{
    const float* x   = (const float*)d_in[0];
    float*       out = (float*)d_out;

    cudaFuncSetAttribute(dme_kernel,
                         cudaFuncAttributeMaxDynamicSharedMemorySize, SMEM_BYTES);

    dme_kernel<<<NPIX / COLS, BLK, SMEM_BYTES>>>(x, out);
}

// round 15
// speedup vs baseline: 1.0228x; 1.0228x over previous
#include <cuda_runtime.h>

// x shape (N=2, D=192, H=256, W=512), float32.
#define DIMD 192
#define HWD  131072          // H*W
#define BLK  512             // threads per block
#define COLS 128             // pixel columns per block (4 threads / column)
#define NPIX 262144          // N*H*W
#define CST  129             // ODD smem row stride: bank = (d + c) & 31
#define PADR 2               // zero-pad rows above and below (blur radius)
#define SMEM_BYTES ((DIMD + 2 * PADR) * CST * 4)   // 101136 B -> 2 CTAs/SM

// Correctly-rounded a/5 (Markstein step, exact seed 0.2f) — bit-identical to
// __fdiv_rn(a,5); 3 FMA-pipe ops. Validated rounds 5-14.
__device__ __forceinline__ float qdiv5(float a)
{
    const float y  = 0.2f;
    float q0 = a * y;
    float r  = fmaf(-5.0f, q0, a);
    return fmaf(r, y, q0);
}

// Ordered 2-way merge: strict > so ties keep the LOWER-index side
// (first-occurrence argmax). selfLow: our indices precede partner's.
__device__ __forceinline__ void merge2(bool selfLow, float aq, int ai,
                                       float bq, int bi, float& q, int& i)
{
    float lq = selfLow ? aq : bq;  int li = selfLow ? ai : bi;
    float hq = selfLow ? bq : aq;  int hi = selfLow ? bi : ai;
    bool u = (hq > lq);
    q = u ? hq : lq;
    i = u ? hi : li;
}

// Unguarded blur at p (pads supply the reference's zero padding exactly).
__device__ __forceinline__ float blur_u(const float* __restrict__ sp, int p)
{
    float a = sp[(p - 2) * CST];
    a = a + sp[(p - 1) * CST];
    a = a + sp[p * CST];
    a = a + sp[(p + 1) * CST];
    a = a + sp[(p + 2) * CST];
    return qdiv5(a);
}

// Direction-unified slope scan (shared code path; dir is data -> warp pays
// max(right,left) trips). HASZ zeroes blur VALUE on [ZA,ZB].
template<bool HASZ>
__device__ __forceinline__ int dir_scan(const float* __restrict__ sp, int idx,
                                        float bq, int dir, int ZA, int ZB)
{
    int   pos = idx;
    float val = bq;
    while (true) {
        int p = pos + dir;
        if ((unsigned)p >= (unsigned)DIMD) break;    // sentinel at both ends
        float q = blur_u(sp, p);
        if (HASZ && p >= ZA && p <= ZB) q = 0.0f;
        if (q > val) break;
        val = q; pos = p;
    }
    return pos;
}

// Continue argmax of blur(raw x) over d in [a, bEnd), rolling window, unguarded.
__device__ __forceinline__ void seg_argmax(const float* __restrict__ sp, int a, int bEnd,
                                           float& bestQ, int& idx)
{
    if (a >= bEnd) return;
    float w0 = sp[(a - 2) * CST];
    float w1 = sp[(a - 1) * CST];
    float w2 = sp[a * CST];
    float w3 = sp[(a + 1) * CST];
    #pragma unroll 2
    for (int d = a; d < bEnd; ++d) {
        float w4 = sp[(d + 2) * CST];
        float q  = qdiv5((((w0 + w1) + w2) + w3) + w4);
        bool  u  = (q > bestQ);             // strict -> first occurrence
        bestQ = u ? q : bestQ;
        idx   = u ? d : idx;
        w0 = w1; w1 = w2; w2 = w3; w3 = w4;
    }
}

__global__ void __launch_bounds__(BLK, 2)
dme_kernel(const float* __restrict__ x, float* __restrict__ out)
{
    extern __shared__ float s[];                // [(PADR+DIMD+PADR)][CST]
    const int tid  = threadIdx.x;
    const int c    = tid >> 2;                  // column 0..127
    const int r    = tid & 3;                   // role: d-quarter [48r, 48r+48)
    const int sr   = r & 1;                     // sub-role: 0 = right/y, 1 = left/z
    const int pix0 = blockIdx.x * COLS;         // blocks never straddle n
    const int n    = pix0 >> 17;
    const int hw0  = pix0 & (HWD - 1);
    const float* __restrict__ gb = x + (size_t)n * DIMD * HWD + hw0;

    // ---- zero the 4 pad rows (512 entries, one STS per thread) ----
    {
        static const int prow[4] = {0, 1, PADR + DIMD, PADR + DIMD + 1};
        s[prow[tid >> 7] * CST + (tid & 127)] = 0.0f;
    }
    // ---- stage-in: 12 x (LDG.128 + 4 STS.32) per thread, high MLP ----
    #pragma unroll
    for (int i = 0; i < (DIMD * COLS / 4) / BLK; ++i) {   // 12 iters
        int flat = i * BLK + tid;               // float4 index, 32 per d-row
        int d    = flat >> 5;
        int p4   = (flat & 31) * 4;
        float4 v = *(const float4*)(gb + (size_t)d * HWD + p4);
        float* sd = s + (d + PADR) * CST + p4;
        sd[0] = v.x; sd[1] = v.y; sd[2] = v.z; sd[3] = v.w;
    }
    __syncthreads();

    const float* __restrict__ sp = s + PADR * CST + c;   // column base (d=0 row)

    // ---- pass-1 argmax over blur: one 48-iter unguarded chain per role ----
    const int base = 48 * r;
    float bq1 = -1.0f; int bi1 = 0;
    {
        float w0 = sp[(base - 2) * CST];        // pads give zeros for r=0
        float w1 = sp[(base - 1) * CST];
        float w2 = sp[base * CST];
        float w3 = sp[(base + 1) * CST];
        #pragma unroll 8
        for (int j = 0; j < 48; ++j) {          // r=3 tail reads pad zeros
            float w4 = sp[(base + j + 2) * CST];
            float q  = qdiv5((((w0 + w1) + w2) + w3) + w4);
            bool  u  = (q > bq1);
            bq1 = u ? q : bq1;
            bi1 = u ? (base + j) : bi1;
            w0 = w1; w1 = w2; w2 = w3; w3 = w4;
        }
    }
    // ordered 2-stage merge (roles ascend in d)
    float bestQ; int idx;
    {
        float oq = __shfl_xor_sync(0xffffffffu, bq1, 1);
        int   oi = __shfl_xor_sync(0xffffffffu, bi1, 1);
        float mq; int mi;
        merge2((r & 1) == 0, bq1, bi1, oq, oi, mq, mi);
        float pq = __shfl_xor_sync(0xffffffffu, mq, 2);
        int   pi = __shfl_xor_sync(0xffffffffu, mi, 2);
        merge2(r < 2, mq, mi, pq, pi, bestQ, idx);
    }

    // ---- modal interval 1: right scan on sr=0, left on sr=1 (shared path) ----
    const int dir = 1 - 2 * sr;
    int lo1, hi1;
    {
        int mine  = dir_scan<false>(sp, idx, bestQ, dir, 0, -1);
        int other = __shfl_xor_sync(0xffffffffu, mine, 1);
        int ir = sr ? other : mine;
        int il = sr ? mine  : other;
        int dev = 2 * idx - ir - il; if (dev < 0) dev = -dev;
        if (dev < 3) { lo1 = il; hi1 = ir; }
        else { int rr = min(ir - idx, idx - il); lo1 = idx - rr; hi1 = idx + rr; }
    }

    // ---- pass-2 argmax over complement of [lo1,hi1], clipped per quarter ----
    float bq2l = -1.0f; int bi2l = 0;
    seg_argmax(sp, base, min(lo1, base + 48), bq2l, bi2l);
    seg_argmax(sp, max(hi1 + 1, base), base + 48, bq2l, bi2l);
    float bq2; int idx2;
    {
        float oq = __shfl_xor_sync(0xffffffffu, bq2l, 1);
        int   oi = __shfl_xor_sync(0xffffffffu, bi2l, 1);
        float mq; int mi;
        merge2((r & 1) == 0, bq2l, bi2l, oq, oi, mq, mi);
        float pq = __shfl_xor_sync(0xffffffffu, mq, 2);
        int   pi = __shfl_xor_sync(0xffffffffu, mi, 2);
        merge2(r < 2, mq, mi, pq, pi, bq2, idx2);
    }

    // ---- modal interval 2 (blur zeroed on [lo1,hi1]) ----
    int lo2, hi2;
    {
        int mine  = dir_scan<true>(sp, idx2, bq2, dir, lo1, hi1);
        int other = __shfl_xor_sync(0xffffffffu, mine, 1);
        int ir = sr ? other : mine;
        int il = sr ? mine  : other;
        int dev = 2 * idx2 - ir - il; if (dev < 0) dev = -dev;
        if (dev < 3) { lo2 = il; hi2 = ir; }
        else { int rr = min(ir - idx2, idx2 - il); lo2 = idx2 - rr; hi2 = idx2 + rr; }
    }

    // ---- reductions: sr=0 -> y over [lo1,hi1]; sr=1 -> z over [lo2,hi2]\[lo1,hi1]
    //      branchless exclusion (adding +0.0f is exact; order unchanged) ----
    const int A  = sr ? lo2 : lo1;
    const int B  = sr ? hi2 : hi1;
    const int E0 = sr ? lo1 : 1;
    const int E1 = sr ? hi1 : 0;
    float ss = 0.0f, sd = 0.0f;
    for (int d = A; d <= B; ++d) {
        float v = sp[d * CST];
        v = (d >= E0 && d <= E1) ? 0.0f : v;
        ss += v; sd = fmaf(v, (float)d, sd);
    }
    float os = __shfl_xor_sync(0xffffffffu, ss, 1);
    float od = __shfl_xor_sync(0xffffffffu, sd, 1);
    const float sy  = sr ? os : ss, syd = sr ? od : sd;
    const float sz  = sr ? ss : os, szd = sr ? sd : od;

    if (r == 0) {
        const bool  py  = (sy >= sz);
        const float num = py ? syd : szd;
        const float den = py ? sy  : sz;        // > 0 guaranteed (x > 0)
        out[pix0 + c] = __fdiv_rn(num, den);
    }
}

extern "C" void kernel_launch(void* const* d_in, const int* in_sizes, int n_in,
                              void* d_out, int out_size)
{
    const float* x   = (const float*)d_in[0];
    float*       out = (float*)d_out;

    cudaFuncSetAttribute(dme_kernel,
                         cudaFuncAttributeMaxDynamicSharedMemorySize, SMEM_BYTES);

    dme_kernel<<<NPIX / COLS, BLK, SMEM_BYTES>>>(x, out);
}

// round 16
// speedup vs baseline: 1.0345x; 1.0114x over previous
#include <cuda_runtime.h>

// x shape (N=2, D=192, H=256, W=512), float32.
#define DIMD 192
#define HWD  131072          // H*W
#define BLK  512             // threads per block
#define COLS 128             // pixel columns per block (4 threads / column)
#define NPIX 262144          // N*H*W
#define CST  129             // ODD smem row stride: bank = (d + c) & 31
#define PADR 2               // zero-pad rows above and below (blur radius)
#define SMEM_BYTES ((DIMD + 2 * PADR) * CST * 4)   // 101136 B -> 2 CTAs/SM

// Correctly-rounded a/5 (Markstein step, exact seed 0.2f) — bit-identical to
// __fdiv_rn(a,5); 3 FMA-pipe ops. Validated rounds 5-14.
__device__ __forceinline__ float qdiv5(float a)
{
    const float y  = 0.2f;
    float q0 = a * y;
    float r  = fmaf(-5.0f, q0, a);
    return fmaf(r, y, q0);
}

// Ordered 2-way merge: strict > so ties keep the LOWER-index side
// (first-occurrence argmax). selfLow: our indices precede partner's.
__device__ __forceinline__ void merge2(bool selfLow, float aq, int ai,
                                       float bq, int bi, float& q, int& i)
{
    float lq = selfLow ? aq : bq;  int li = selfLow ? ai : bi;
    float hq = selfLow ? bq : aq;  int hi = selfLow ? bi : ai;
    bool u = (hq > lq);
    q = u ? hq : lq;
    i = u ? hi : li;
}

// Unguarded blur at p (pads supply the reference's zero padding exactly).
__device__ __forceinline__ float blur_u(const float* __restrict__ sp, int p)
{
    float a = sp[(p - 2) * CST];
    a = a + sp[(p - 1) * CST];
    a = a + sp[p * CST];
    a = a + sp[(p + 1) * CST];
    a = a + sp[(p + 2) * CST];
    return qdiv5(a);
}

// Direction-unified slope scan (shared code path; dir is data -> warp pays
// max(right,left) trips). HASZ zeroes blur VALUE on [ZA,ZB].
template<bool HASZ>
__device__ __forceinline__ int dir_scan(const float* __restrict__ sp, int idx,
                                        float bq, int dir, int ZA, int ZB)
{
    int   pos = idx;
    float val = bq;
    while (true) {
        int p = pos + dir;
        if ((unsigned)p >= (unsigned)DIMD) break;    // sentinel at both ends
        float q = blur_u(sp, p);
        if (HASZ && p >= ZA && p <= ZB) q = 0.0f;
        if (q > val) break;
        val = q; pos = p;
    }
    return pos;
}

// Continue argmax of blur(raw x) over d in [a, bEnd), rolling window, unguarded.
__device__ __forceinline__ void seg_argmax(const float* __restrict__ sp, int a, int bEnd,
                                           float& bestQ, int& idx)
{
    if (a >= bEnd) return;
    float w0 = sp[(a - 2) * CST];
    float w1 = sp[(a - 1) * CST];
    float w2 = sp[a * CST];
    float w3 = sp[(a + 1) * CST];
    #pragma unroll 2
    for (int d = a; d < bEnd; ++d) {
        float w4 = sp[(d + 2) * CST];
        float q  = qdiv5((((w0 + w1) + w2) + w3) + w4);
        bool  u  = (q > bestQ);             // strict -> first occurrence
        bestQ = u ? q : bestQ;
        idx   = u ? d : idx;
        w0 = w1; w1 = w2; w2 = w3; w3 = w4;
    }
}

__global__ void __launch_bounds__(BLK, 2)
dme_kernel(const float* __restrict__ x, float* __restrict__ out)
{
    extern __shared__ float s[];                // [(PADR+DIMD+PADR)][CST]
    const int tid  = threadIdx.x;
    const int c    = tid >> 2;                  // column 0..127
    const int r    = tid & 3;                   // role: d-quarter [48r, 48r+48)
    const int sr   = r & 1;                     // sub-role: 0 = right/y, 1 = left/z
    const int pix0 = blockIdx.x * COLS;         // blocks never straddle n
    const int n    = pix0 >> 17;
    const int hw0  = pix0 & (HWD - 1);
    const float* __restrict__ gb = x + (size_t)n * DIMD * HWD + hw0;

    // ---- zero the 4 pad rows (512 entries, one STS per thread) ----
    {
        static const int prow[4] = {0, 1, PADR + DIMD, PADR + DIMD + 1};
        s[prow[tid >> 7] * CST + (tid & 127)] = 0.0f;
    }
    // ---- stage-in: 12 x (LDG.128 + 4 STS.32) per thread, high MLP ----
    #pragma unroll
    for (int i = 0; i < (DIMD * COLS / 4) / BLK; ++i) {   // 12 iters
        int flat = i * BLK + tid;               // float4 index, 32 per d-row
        int d    = flat >> 5;
        int p4   = (flat & 31) * 4;
        float4 v = *(const float4*)(gb + (size_t)d * HWD + p4);
        float* sd = s + (d + PADR) * CST + p4;
        sd[0] = v.x; sd[1] = v.y; sd[2] = v.z; sd[3] = v.w;
    }
    __syncthreads();

    const float* __restrict__ sp = s + PADR * CST + c;   // column base (d=0 row)

    // ---- pass-1 argmax over blur: one 48-iter unguarded chain per role ----
    const int base = 48 * r;
    float bq1 = -1.0f; int bi1 = 0;
    {
        float w0 = sp[(base - 2) * CST];        // pads give zeros for r=0
        float w1 = sp[(base - 1) * CST];
        float w2 = sp[base * CST];
        float w3 = sp[(base + 1) * CST];
        #pragma unroll 8
        for (int j = 0; j < 48; ++j) {          // r=3 tail reads pad zeros
            float w4 = sp[(base + j + 2) * CST];
            float q  = qdiv5((((w0 + w1) + w2) + w3) + w4);
            bool  u  = (q > bq1);
            bq1 = u ? q : bq1;
            bi1 = u ? (base + j) : bi1;
            w0 = w1; w1 = w2; w2 = w3; w3 = w4;
        }
    }
    // ordered 2-stage merge (roles ascend in d)
    float bestQ; int idx;
    {
        float oq = __shfl_xor_sync(0xffffffffu, bq1, 1);
        int   oi = __shfl_xor_sync(0xffffffffu, bi1, 1);
        float mq; int mi;
        merge2((r & 1) == 0, bq1, bi1, oq, oi, mq, mi);
        float pq = __shfl_xor_sync(0xffffffffu, mq, 2);
        int   pi = __shfl_xor_sync(0xffffffffu, mi, 2);
        merge2(r < 2, mq, mi, pq, pi, bestQ, idx);
    }

    // ---- modal interval 1: right scan on sr=0, left on sr=1 (shared path) ----
    const int dir = 1 - 2 * sr;
    int lo1, hi1;
    {
        int mine  = dir_scan<false>(sp, idx, bestQ, dir, 0, -1);
        int other = __shfl_xor_sync(0xffffffffu, mine, 1);
        int ir = sr ? other : mine;
        int il = sr ? mine  : other;
        int dev = 2 * idx - ir - il; if (dev < 0) dev = -dev;
        if (dev < 3) { lo1 = il; hi1 = ir; }
        else { int rr = min(ir - idx, idx - il); lo1 = idx - rr; hi1 = idx + rr; }
    }

    // ---- pass-2 argmax over complement of [lo1,hi1], clipped per quarter ----
    float bq2l = -1.0f; int bi2l = 0;
    seg_argmax(sp, base, min(lo1, base + 48), bq2l, bi2l);
    seg_argmax(sp, max(hi1 + 1, base), base + 48, bq2l, bi2l);
    float bq2; int idx2;
    {
        float oq = __shfl_xor_sync(0xffffffffu, bq2l, 1);
        int   oi = __shfl_xor_sync(0xffffffffu, bi2l, 1);
        float mq; int mi;
        merge2((r & 1) == 0, bq2l, bi2l, oq, oi, mq, mi);
        float pq = __shfl_xor_sync(0xffffffffu, mq, 2);
        int   pi = __shfl_xor_sync(0xffffffffu, mi, 2);
        merge2(r < 2, mq, mi, pq, pi, bq2, idx2);
    }

    // ---- modal interval 2 (blur zeroed on [lo1,hi1]) ----
    int lo2, hi2;
    {
        int mine  = dir_scan<true>(sp, idx2, bq2, dir, lo1, hi1);
        int other = __shfl_xor_sync(0xffffffffu, mine, 1);
        int ir = sr ? other : mine;
        int il = sr ? mine  : other;
        int dev = 2 * idx2 - ir - il; if (dev < 0) dev = -dev;
        if (dev < 3) { lo2 = il; hi2 = ir; }
        else { int rr = min(ir - idx2, idx2 - il); lo2 = idx2 - rr; hi2 = idx2 + rr; }
    }

    // ---- reductions: sr=0 -> y over [lo1,hi1]; sr=1 -> z over [lo2,hi2]\[lo1,hi1]
    //      branchless exclusion (adding +0.0f is exact; order unchanged) ----
    const int A  = sr ? lo2 : lo1;
    const int B  = sr ? hi2 : hi1;
    const int E0 = sr ? lo1 : 1;
    const int E1 = sr ? hi1 : 0;
    float ss = 0.0f, sd = 0.0f;
    for (int d = A; d <= B; ++d) {
        float v = sp[d * CST];
        v = (d >= E0 && d <= E1) ? 0.0f : v;
        ss += v; sd = fmaf(v, (float)d, sd);
    }
    float os = __shfl_xor_sync(0xffffffffu, ss, 1);
    float od = __shfl_xor_sync(0xffffffffu, sd, 1);
    const float sy  = sr ? os : ss, syd = sr ? od : sd;
    const float sz  = sr ? ss : os, szd = sr ? sd : od;

    if (r == 0) {
        const bool  py  = (sy >= sz);
        const float num = py ? syd : szd;
        const float den = py ? sy  : sz;        // > 0 guaranteed (x > 0)
        out[pix0 + c] = __fdiv_rn(num, den);
    }
}

extern "C" void kernel_launch(void* const* d_in, const int* in_sizes, int n_in,
                              void* d_out, int out_size)
{
    const float* x   = (const float*)d_in[0];
    float*       out = (float*)d_out;

    cudaFuncSetAttribute(dme_kernel,
                         cudaFuncAttributeMaxDynamicSharedMemorySize, SMEM_BYTES);

    dme_kernel<<<NPIX / COLS, BLK, SMEM_BYTES>>>(x, out);
}

// round 17
// speedup vs baseline: 1.1489x; 1.1106x over previous
#include <cuda_runtime.h>

// x shape (N=2, D=192, H=256, W=512), float32.
#define DIMD 192
#define HWD  131072          // H*W
#define BLK  512             // threads per block
#define COLS 128             // pixel columns per block (4 threads / column)
#define NPIX 262144          // N*H*W
#define CST  136             // row stride (floats): bank = (8*row + c) & 31
#define RSTR 49              // role d-stride: 49*136 % 32 == 8 -> roles on banks {0,8,16,24}
#define PADR 2               // zero-pad rows below d=0
#define ROWS 200             // rows [-2, 198): 2 bottom pads + 192 + 6 top pads
#define SMEM_BYTES (ROWS * CST * 4)   // 108800 B -> 2 CTAs/SM

// Correctly-rounded a/5 (Markstein step, exact seed 0.2f) — bit-identical to
// __fdiv_rn(a,5); 3 FMA-pipe ops. Validated rounds 5-16.
__device__ __forceinline__ float qdiv5(float a)
{
    const float y  = 0.2f;
    float q0 = a * y;
    float r  = fmaf(-5.0f, q0, a);
    return fmaf(r, y, q0);
}

// Ordered 2-way merge: strict > keeps the LOWER-index side on ties
// (first-occurrence argmax). selfLow: our indices precede partner's.
__device__ __forceinline__ void merge2(bool selfLow, float aq, int ai,
                                       float bq, int bi, float& q, int& i)
{
    float lq = selfLow ? aq : bq;  int li = selfLow ? ai : bi;
    float hq = selfLow ? bq : aq;  int hi = selfLow ? bi : ai;
    bool u = (hq > lq);
    q = u ? hq : lq;
    i = u ? hi : li;
}

// Unguarded blur at p (pads supply the reference's zero padding exactly).
__device__ __forceinline__ float blur_u(const float* __restrict__ sp, int p)
{
    float a = sp[(p - 2) * CST];
    a = a + sp[(p - 1) * CST];
    a = a + sp[p * CST];
    a = a + sp[(p + 1) * CST];
    a = a + sp[(p + 2) * CST];
    return qdiv5(a);
}

// Direction-unified slope scan (shared code path; warp pays max(right,left)).
// HASZ zeroes blur VALUE on [ZA,ZB] (x_blur * ~mask semantics).
template<bool HASZ>
__device__ __forceinline__ int dir_scan(const float* __restrict__ sp, int idx,
                                        float bq, int dir, int ZA, int ZB)
{
    int   pos = idx;
    float val = bq;
    while (true) {
        int p = pos + dir;
        if ((unsigned)p >= (unsigned)DIMD) break;    // sentinel at both ends
        float q = blur_u(sp, p);
        if (HASZ && p >= ZA && p <= ZB) q = 0.0f;
        if (q > val) break;
        val = q; pos = p;
    }
    return pos;
}

// Continue argmax of blur(raw x) over d in [a, bEnd), rolling window, unguarded.
__device__ __forceinline__ void seg_argmax(const float* __restrict__ sp, int a, int bEnd,
                                           float& bestQ, int& idx)
{
    if (a >= bEnd) return;
    float w0 = sp[(a - 2) * CST];
    float w1 = sp[(a - 1) * CST];
    float w2 = sp[a * CST];
    float w3 = sp[(a + 1) * CST];
    #pragma unroll 2
    for (int d = a; d < bEnd; ++d) {
        float w4 = sp[(d + 2) * CST];
        float q  = qdiv5((((w0 + w1) + w2) + w3) + w4);
        bool  u  = (q > bestQ);             // strict -> first occurrence
        bestQ = u ? q : bestQ;
        idx   = u ? d : idx;
        w0 = w1; w1 = w2; w2 = w3; w3 = w4;
    }
}

__global__ void __launch_bounds__(BLK, 2)
dme_kernel(const float* __restrict__ x, float* __restrict__ out)
{
    extern __shared__ float s[];                // [ROWS][CST]
    const int tid  = threadIdx.x;
    const int c    = tid >> 2;                  // column 0..127
    const int r    = tid & 3;                   // role: d-range [49r, 49r+49) masked to <192
    const int sr   = r & 1;                     // sub-role: 0 = right/y, 1 = left/z
    const int pix0 = blockIdx.x * COLS;         // blocks never straddle n
    const int n    = pix0 >> 17;
    const int hw0  = pix0 & (HWD - 1);
    const float* __restrict__ gb = x + (size_t)n * DIMD * HWD + hw0;

    // ---- zero the 8 pad rows (cols 0..127 only; 1024 entries, 2 per thread) ----
    #pragma unroll
    for (int k = tid; k < 1024; k += BLK) {
        int rowsel = k >> 7;                    // 0..7
        int row    = rowsel + ((rowsel >= 2) ? 192 : 0);   // rows 0,1,194..199
        s[row * CST + (k & 127)] = 0.0f;
    }
    // ---- stage-in: 12 x (LDG.128 + STS.128) per thread (CST even -> aligned) ----
    #pragma unroll
    for (int i = 0; i < (DIMD * COLS / 4) / BLK; ++i) {   // 12 iters
        int flat = i * BLK + tid;               // float4 index, 32 per d-row
        int d    = flat >> 5;
        int p4   = (flat & 31) * 4;
        float4 v = *(const float4*)(gb + (size_t)d * HWD + p4);
        *(float4*)(s + (d + PADR) * CST + p4) = v;
    }
    __syncthreads();

    const float* __restrict__ sp = s + PADR * CST + c;   // column base (d=0 row)

    // ---- pass-1 argmax over blur: one 49-iter conflict-free chain per role ----
    const int base = RSTR * r;                  // 0, 49, 98, 147
    const int lim  = (r == 3) ? (DIMD - 3 * RSTR) : RSTR;   // 45 for role 3
    float bq1 = -1.0f; int bi1 = 0;
    {
        float w0 = sp[(base - 2) * CST];        // pads give zeros for r=0
        float w1 = sp[(base - 1) * CST];
        float w2 = sp[base * CST];
        float w3 = sp[(base + 1) * CST];
        #pragma unroll 7
        for (int j = 0; j < RSTR; ++j) {        // role-3 tail reads pad zeros
            float w4 = sp[(base + j + 2) * CST];
            float q  = qdiv5((((w0 + w1) + w2) + w3) + w4);
            bool  u  = (q > bq1) && (j < lim);  // mask d >= 192 iterations
            bq1 = u ? q : bq1;
            bi1 = u ? (base + j) : bi1;
            w0 = w1; w1 = w2; w2 = w3; w3 = w4;
        }
    }
    // ordered 2-stage merge (roles ascend in d)
    float bestQ; int idx;
    {
        float oq = __shfl_xor_sync(0xffffffffu, bq1, 1);
        int   oi = __shfl_xor_sync(0xffffffffu, bi1, 1);
        float mq; int mi;
        merge2((r & 1) == 0, bq1, bi1, oq, oi, mq, mi);
        float pq = __shfl_xor_sync(0xffffffffu, mq, 2);
        int   pi = __shfl_xor_sync(0xffffffffu, mi, 2);
        merge2(r < 2, mq, mi, pq, pi, bestQ, idx);
    }

    // ---- modal interval 1: right scan on sr=0, left on sr=1 (shared path) ----
    const int dir = 1 - 2 * sr;
    int lo1, hi1;
    {
        int mine  = dir_scan<false>(sp, idx, bestQ, dir, 0, -1);
        int other = __shfl_xor_sync(0xffffffffu, mine, 1);
        int ir = sr ? other : mine;
        int il = sr ? mine  : other;
        int dev = 2 * idx - ir - il; if (dev < 0) dev = -dev;
        if (dev < 3) { lo1 = il; hi1 = ir; }
        else { int rr = min(ir - idx, idx - il); lo1 = idx - rr; hi1 = idx + rr; }
    }

    // ---- pass-2 argmax over complement of [lo1,hi1], clipped per role range ----
    const int qend = min(base + RSTR, DIMD);
    float bq2l = -1.0f; int bi2l = 0;
    seg_argmax(sp, base, min(lo1, qend), bq2l, bi2l);
    seg_argmax(sp, max(hi1 + 1, base), qend, bq2l, bi2l);
    float bq2; int idx2;
    {
        float oq = __shfl_xor_sync(0xffffffffu, bq2l, 1);
        int   oi = __shfl_xor_sync(0xffffffffu, bi2l, 1);
        float mq; int mi;
        merge2((r & 1) == 0, bq2l, bi2l, oq, oi, mq, mi);
        float pq = __shfl_xor_sync(0xffffffffu, mq, 2);
        int   pi = __shfl_xor_sync(0xffffffffu, mi, 2);
        merge2(r < 2, mq, mi, pq, pi, bq2, idx2);
    }

    // ---- modal interval 2 (blur zeroed on [lo1,hi1]) ----
    int lo2, hi2;
    {
        int mine  = dir_scan<true>(sp, idx2, bq2, dir, lo1, hi1);
        int other = __shfl_xor_sync(0xffffffffu, mine, 1);
        int ir = sr ? other : mine;
        int il = sr ? mine  : other;
        int dev = 2 * idx2 - ir - il; if (dev < 0) dev = -dev;
        if (dev < 3) { lo2 = il; hi2 = ir; }
        else { int rr = min(ir - idx2, idx2 - il); lo2 = idx2 - rr; hi2 = idx2 + rr; }
    }

    // ---- reductions: sr=0 -> y over [lo1,hi1]; sr=1 -> z over [lo2,hi2]\[lo1,hi1]
    //      branchless exclusion (adding +0.0f is exact; order unchanged) ----
    const int A  = sr ? lo2 : lo1;
    const int B  = sr ? hi2 : hi1;
    const int E0 = sr ? lo1 : 1;
    const int E1 = sr ? hi1 : 0;
    float ss = 0.0f, sd = 0.0f;
    for (int d = A; d <= B; ++d) {
        float v = sp[d * CST];
        v = (d >= E0 && d <= E1) ? 0.0f : v;
        ss += v; sd = fmaf(v, (float)d, sd);
    }
    float os = __shfl_xor_sync(0xffffffffu, ss, 1);
    float od = __shfl_xor_sync(0xffffffffu, sd, 1);
    const float sy  = sr ? os : ss, syd = sr ? od : sd;
    const float sz  = sr ? ss : os, szd = sr ? sd : od;

    if (r == 0) {
        const bool  py  = (sy >= sz);
        const float num = py ? syd : szd;
        const float den = py ? sy  : sz;        // > 0 guaranteed (x > 0)
        out[pix0 + c] = __fdiv_rn(num, den);
    }
}

extern "C" void kernel_launch(void* const* d_in, const int* in_sizes, int n_in,
                              void* d_out, int out_size)
{
    const float* x   = (const float*)d_in[0];
    float*       out = (float*)d_out;

    cudaFuncSetAttribute(dme_kernel,
                         cudaFuncAttributeMaxDynamicSharedMemorySize, SMEM_BYTES);

    dme_kernel<<<NPIX / COLS, BLK, SMEM_BYTES>>>(x, out);
}